// round 3
// baseline (speedup 1.0000x reference)
#include <cuda_runtime.h>

#define BB   64
#define MM   100
#define NN   4000
#define KK   4100          // N + M (proposal_append_gt)
#define NB   1024          // priority buckets per group
#define SEGS 2048          // 2 groups * NB
#define NCLS 80
#define BATCH_PER_IMG 512
#define NUM_FG_TARGET 128

// Scratch (static __device__ — no allocation)
__device__ float         g_mv[BB * KK];
__device__ unsigned char g_mi[BB * KK];

// ---------------------------------------------------------------------------
// Kernel 1: per-(image, proposal) max-IoU matching.
// Cross-multiplication ordering avoids per-pair division; one IEEE division
// per proposal at the end. Two accumulator chains (even/odd m) halve the
// FSETP-latency-bound dependency chain.
// ---------------------------------------------------------------------------
__global__ __launch_bounds__(256) void iou_kernel(const float* __restrict__ gt,
                                                  const float* __restrict__ prop) {
    const int b   = blockIdx.y;
    const int tid = threadIdx.x;
    __shared__ float4 sgt[MM];
    __shared__ float  sarea[MM];

    if (tid < MM) {
        float4 g = reinterpret_cast<const float4*>(gt)[b * MM + tid];
        sgt[tid]   = g;
        sarea[tid] = (g.z - g.x) * (g.w - g.y);
    }
    __syncthreads();

    const float4* pr = reinterpret_cast<const float4*>(prop) + (size_t)b * NN;

    for (int k = blockIdx.x * 256 + tid; k < KK; k += gridDim.x * 256) {
        float4 a = (k < NN) ? pr[k] : sgt[k - NN];
        float areaA = (a.z - a.x) * (a.w - a.y);

        // chain 0: even m, chain 1: odd m
        float bi0 = 0.f, bu0 = 1.f; int bm0 = 0;
        float bi1 = 0.f, bu1 = 1.f; int bm1 = 1;

        #pragma unroll 4
        for (int m = 0; m < MM; m += 2) {
            {
                float4 g = sgt[m];
                float lx = fmaxf(g.x, a.x), ly = fmaxf(g.y, a.y);
                float rx = fminf(g.z, a.z), ry = fminf(g.w, a.w);
                float w = fmaxf(rx - lx, 0.f), h = fmaxf(ry - ly, 0.f);
                float inter = w * h;
                float uni   = (sarea[m] + areaA) - inter;
                if (inter * bu0 > bi0 * uni) { bi0 = inter; bu0 = uni; bm0 = m; }
            }
            {
                float4 g = sgt[m + 1];
                float lx = fmaxf(g.x, a.x), ly = fmaxf(g.y, a.y);
                float rx = fminf(g.z, a.z), ry = fminf(g.w, a.w);
                float w = fmaxf(rx - lx, 0.f), h = fmaxf(ry - ly, 0.f);
                float inter = w * h;
                float uni   = (sarea[m + 1] + areaA) - inter;
                if (inter * bu1 > bi1 * uni) { bi1 = inter; bu1 = uni; bm1 = m + 1; }
            }
        }
        // merge (first-max tie-break: equal value -> lower index)
        float c0 = bi0 * bu1, c1 = bi1 * bu0;
        bool useE = (c0 > c1) || (c0 == c1 && bm0 < bm1);
        float bi = useE ? bi0 : bi1;
        float bu = useE ? bu0 : bu1;
        int   bm = useE ? bm0 : bm1;

        size_t o = (size_t)b * KK + k;
        g_mv[o] = __fdiv_rn(bi, bu);   // IEEE, matches reference regardless of fast-math
        g_mi[o] = (unsigned char)bm;
    }
}

// ---------------------------------------------------------------------------
// Kernel 2: per-image fg/bg subsampling via bucketed counting sort.
// One CTA (512 threads) per image.
// ---------------------------------------------------------------------------
__global__ __launch_bounds__(512) void sample_kernel(const float* __restrict__ pri,
                                                     const void*  __restrict__ gtcls,
                                                     float* __restrict__ out) {
    const int b   = blockIdx.x;
    const int tid = threadIdx.x;

    __shared__ float          s_pri[KK];
    __shared__ unsigned short s_list[KK];
    __shared__ int            s_cnt[SEGS];     // histogram, then scatter cursor
    __shared__ int            s_P[SEGS + 1];   // ascending exclusive prefix
    __shared__ unsigned short s_ordF[NUM_FG_TARGET];
    __shared__ unsigned short s_ordB[BATCH_PER_IMG];
    __shared__ int            s_wsum[17];
    __shared__ int            s_is64;

    // Detect gt_classes dtype (int64 vs int32): int64 -> high words all zero.
    if (tid == 0) {
        int f = 1;
        const int* w = (const int*)gtcls;
        #pragma unroll 1
        for (int i = 1; i < 128; i += 2) if (w[i] != 0) { f = 0; break; }
        s_is64 = f;
    }
    for (int i = tid; i < SEGS; i += 512) s_cnt[i] = 0;
    __syncthreads();

    const float* prib = pri  + (size_t)b * KK;
    const float* mvb  = g_mv + (size_t)b * KK;

    // Pass 1: load priorities, classify fg/bg, histogram buckets.
    unsigned short myseg[9];
    int nk = 0;
    for (int k = tid; k < KK; k += 512) {
        float p = prib[k];
        s_pri[k] = p;
        float mv = mvb[k];
        int g  = (mv >= 0.5f) ? 0 : 1;               // 0 = fg, 1 = bg
        int bk = (int)(p * (float)NB);
        if (bk > NB - 1) bk = NB - 1;
        int seg = g * NB + bk;
        myseg[nk++] = (unsigned short)seg;
        atomicAdd(&s_cnt[seg], 1);
    }
    __syncthreads();

    // Block exclusive scan over SEGS=2048 counts (4 per thread).
    const int base4 = tid * 4;
    int v0 = s_cnt[base4], v1 = s_cnt[base4 + 1], v2 = s_cnt[base4 + 2], v3 = s_cnt[base4 + 3];
    int t = v0 + v1 + v2 + v3;
    int lane = tid & 31, wid = tid >> 5;
    int incl = t;
    #pragma unroll
    for (int d = 1; d < 32; d <<= 1) {
        int n = __shfl_up_sync(0xffffffffu, incl, d);
        if (lane >= d) incl += n;
    }
    if (lane == 31) s_wsum[wid] = incl;
    __syncthreads();
    if (tid == 0) {
        int s = 0;
        #pragma unroll
        for (int i = 0; i < 16; i++) { int c = s_wsum[i]; s_wsum[i] = s; s += c; }
        s_wsum[16] = s;
    }
    __syncthreads();
    int ex = s_wsum[wid] + incl - t;
    s_P[base4]     = ex;
    s_P[base4 + 1] = ex + v0;
    s_P[base4 + 2] = ex + v0 + v1;
    s_P[base4 + 3] = ex + v0 + v1 + v2;
    if (tid == 0) s_P[SEGS] = KK;
    __syncthreads();

    // Re-init cnt as scatter cursor = P.
    s_cnt[base4]     = s_P[base4];
    s_cnt[base4 + 1] = s_P[base4 + 1];
    s_cnt[base4 + 2] = s_P[base4 + 2];
    s_cnt[base4 + 3] = s_P[base4 + 3];
    __syncthreads();

    // Pass 2: scatter element indices into bucket segments.
    nk = 0;
    for (int k = tid; k < KK; k += 512) {
        int seg = myseg[nk++];
        int pos = atomicAdd(&s_cnt[seg], 1);
        s_list[pos] = (unsigned short)k;
    }
    __syncthreads();

    const int nfg = s_P[NB];   // total fg elements

    // Pass 3: exact descending rank within group; scatter into order arrays.
    // Tie-break = reversed stable argsort: equal priority -> higher index first.
    nk = 0;
    for (int k = tid; k < KK; k += 512) {
        int seg = myseg[nk++];
        int lo = s_P[seg], hi = s_P[seg + 1];
        float p = s_pri[k];
        int r = 0;
        for (int j = lo; j < hi; j++) {
            int o = s_list[j];
            float po = s_pri[o];
            if (po > p || (po == p && o > k)) r++;
        }
        int gend = (seg < NB) ? nfg : KK;
        int rank = (gend - hi) + r;     // #higher buckets in group + local rank
        if (seg < NB) {
            if (rank < NUM_FG_TARGET) s_ordF[rank] = (unsigned short)k;
        } else {
            if (rank < BATCH_PER_IMG) s_ordB[rank] = (unsigned short)k;
        }
    }
    __syncthreads();

    // Final: assemble 512 samples.
    int num_fg = nfg < NUM_FG_TARGET ? nfg : NUM_FG_TARGET;
    int nbg    = KK - nfg;
    int rem    = BATCH_PER_IMG - num_fg;
    int num_bg = nbg < rem ? nbg : rem;
    int tot    = num_fg + num_bg;

    float o_iou = 0.f;
    int o_idx = -1, o_cls = -1, o_gt = -1, o_val = 0;
    if (tid < tot) {
        int k = (tid < num_fg) ? (int)s_ordF[tid] : (int)s_ordB[tid - num_fg];
        float mv = mvb[k];
        int mi = (int)g_mi[(size_t)b * KK + k];
        int cls;
        if (mv >= 0.5f) {
            cls = s_is64 ? (int)((const long long*)gtcls)[b * MM + mi]
                         : ((const int*)gtcls)[b * MM + mi];
        } else {
            cls = NCLS;
        }
        o_iou = mv; o_idx = k; o_cls = cls; o_gt = mi; o_val = 1;
    }

    const int S = BB * BATCH_PER_IMG;
    int base = b * BATCH_PER_IMG + tid;
    out[base]         = o_iou;
    out[S + base]     = (float)o_idx;
    out[2 * S + base] = (float)o_cls;
    out[3 * S + base] = (float)o_gt;
    out[4 * S + base] = (float)o_val;
}

// ---------------------------------------------------------------------------
extern "C" void kernel_launch(void* const* d_in, const int* in_sizes, int n_in,
                              void* d_out, int out_size) {
    const float* gt   = (const float*)d_in[0];   // [B, M, 4]
    const float* prop = (const float*)d_in[1];   // [B, N, 4]
    const void*  gtc  = d_in[2];                 // [B, M] int64 or int32
    const float* pri  = (const float*)d_in[3];   // [B, K]
    float* out = (float*)d_out;

    iou_kernel<<<dim3(8, BB), 256>>>(gt, prop);
    sample_kernel<<<BB, 512>>>(pri, gtc, out);
}

// round 5
// speedup vs baseline: 1.1080x; 1.1080x over previous
#include <cuda_runtime.h>

#define BB   64
#define MM   100
#define NN   4000
#define KK   4100          // N + M (proposal_append_gt)
#define NB   1024          // priority buckets per group
#define SEGS 2048          // 2 groups * NB
#define NCLS 80
#define BATCH_PER_IMG 512
#define NUM_FG_TARGET 128
#define ST   1024          // sample_kernel threads
#define SIT  5             // ceil(KK / ST)

// Scratch (static __device__ — no allocation)
__device__ float         g_mv[BB * KK];
__device__ unsigned char g_mi[BB * KK];

// ---------------------------------------------------------------------------
// Kernel 1: per-(image, proposal) max-IoU matching.
// Cross-multiplication ordering avoids per-pair division; one IEEE division
// per proposal at the end. Two accumulator chains (even/odd m) halve the
// FSETP-latency-bound dependency chain.
// ---------------------------------------------------------------------------
__global__ __launch_bounds__(256) void iou_kernel(const float* __restrict__ gt,
                                                  const float* __restrict__ prop) {
    const int b   = blockIdx.y;
    const int tid = threadIdx.x;
    __shared__ float4 sgt[MM];
    __shared__ float  sarea[MM];

    if (tid < MM) {
        float4 g = reinterpret_cast<const float4*>(gt)[b * MM + tid];
        sgt[tid]   = g;
        sarea[tid] = (g.z - g.x) * (g.w - g.y);
    }
    __syncthreads();

    const float4* pr = reinterpret_cast<const float4*>(prop) + (size_t)b * NN;

    for (int k = blockIdx.x * 256 + tid; k < KK; k += gridDim.x * 256) {
        float4 a = (k < NN) ? pr[k] : sgt[k - NN];
        float areaA = (a.z - a.x) * (a.w - a.y);

        // chain 0: even m, chain 1: odd m
        float bi0 = 0.f, bu0 = 1.f; int bm0 = 0;
        float bi1 = 0.f, bu1 = 1.f; int bm1 = 1;

        #pragma unroll 4
        for (int m = 0; m < MM; m += 2) {
            {
                float4 g = sgt[m];
                float lx = fmaxf(g.x, a.x), ly = fmaxf(g.y, a.y);
                float rx = fminf(g.z, a.z), ry = fminf(g.w, a.w);
                float w = fmaxf(rx - lx, 0.f), h = fmaxf(ry - ly, 0.f);
                float inter = w * h;
                float uni   = (sarea[m] + areaA) - inter;
                if (inter * bu0 > bi0 * uni) { bi0 = inter; bu0 = uni; bm0 = m; }
            }
            {
                float4 g = sgt[m + 1];
                float lx = fmaxf(g.x, a.x), ly = fmaxf(g.y, a.y);
                float rx = fminf(g.z, a.z), ry = fminf(g.w, a.w);
                float w = fmaxf(rx - lx, 0.f), h = fmaxf(ry - ly, 0.f);
                float inter = w * h;
                float uni   = (sarea[m + 1] + areaA) - inter;
                if (inter * bu1 > bi1 * uni) { bi1 = inter; bu1 = uni; bm1 = m + 1; }
            }
        }
        // merge (first-max tie-break: equal value -> lower index)
        float c0 = bi0 * bu1, c1 = bi1 * bu0;
        bool useE = (c0 > c1) || (c0 == c1 && bm0 < bm1);
        float bi = useE ? bi0 : bi1;
        float bu = useE ? bu0 : bu1;
        int   bm = useE ? bm0 : bm1;

        size_t o = (size_t)b * KK + k;
        g_mv[o] = __fdiv_rn(bi, bu);   // IEEE, matches reference regardless of fast-math
        g_mi[o] = (unsigned char)bm;
    }
}

// ---------------------------------------------------------------------------
// Kernel 2: per-image fg/bg subsampling via bucketed counting sort.
// One CTA (1024 threads) per image. All K-passes fully unrolled with static
// register indexing (no local-memory spills).
// ---------------------------------------------------------------------------
__global__ __launch_bounds__(ST) void sample_kernel(const float* __restrict__ pri,
                                                    const void*  __restrict__ gtcls,
                                                    float* __restrict__ out) {
    const int b   = blockIdx.x;
    const int tid = threadIdx.x;

    __shared__ float          s_pri[KK];
    __shared__ unsigned short s_list[KK];
    __shared__ int            s_cnt[SEGS];     // histogram, then scatter cursor
    __shared__ int            s_P[SEGS + 1];   // ascending exclusive prefix
    __shared__ unsigned short s_ordF[NUM_FG_TARGET];
    __shared__ unsigned short s_ordB[BATCH_PER_IMG];
    __shared__ int            s_wsum[33];
    __shared__ int            s_nz;

    if (tid == 0) s_nz = 0;
    s_cnt[tid]      = 0;
    s_cnt[tid + ST] = 0;
    __syncthreads();

    // Parallel gt_classes dtype detect (int64 -> high words of first 64
    // elements are all zero). One global load per thread, no serial chain.
    if (tid < 64) {
        const int* w = (const int*)gtcls;
        if (w[2 * tid + 1] != 0) atomicOr(&s_nz, 1);
    }

    const float* prib = pri  + (size_t)b * KK;
    const float* mvb  = g_mv + (size_t)b * KK;

    // Pass 1: load priorities, classify fg/bg, histogram buckets.
    unsigned short myseg[SIT];
    #pragma unroll
    for (int it = 0; it < SIT; it++) {
        int k = tid + it * ST;
        if (k < KK) {
            float p = prib[k];
            s_pri[k] = p;
            float mv = mvb[k];
            int g  = (mv >= 0.5f) ? 0 : 1;           // 0 = fg, 1 = bg
            int bk = (int)(p * (float)NB);
            if (bk > NB - 1) bk = NB - 1;
            int seg = g * NB + bk;
            myseg[it] = (unsigned short)seg;
            atomicAdd(&s_cnt[seg], 1);
        } else {
            myseg[it] = 0xFFFF;
        }
    }
    __syncthreads();

    // Block exclusive scan over SEGS=2048 counts (2 per thread).
    const int i0 = tid * 2;
    int v0 = s_cnt[i0], v1 = s_cnt[i0 + 1];
    int t = v0 + v1;
    int lane = tid & 31, wid = tid >> 5;
    int incl = t;
    #pragma unroll
    for (int d = 1; d < 32; d <<= 1) {
        int n = __shfl_up_sync(0xffffffffu, incl, d);
        if (lane >= d) incl += n;
    }
    if (lane == 31) s_wsum[wid] = incl;
    __syncthreads();
    if (tid == 0) {
        int s = 0;
        #pragma unroll
        for (int i = 0; i < 32; i++) { int c = s_wsum[i]; s_wsum[i] = s; s += c; }
        s_wsum[32] = s;
    }
    __syncthreads();
    int ex = s_wsum[wid] + incl - t;
    s_P[i0]     = ex;
    s_P[i0 + 1] = ex + v0;
    if (tid == 0) s_P[SEGS] = KK;
    __syncthreads();

    // Re-init cnt as scatter cursor = P.
    s_cnt[i0]     = s_P[i0];
    s_cnt[i0 + 1] = s_P[i0 + 1];
    __syncthreads();

    // Pass 2: scatter element indices into bucket segments.
    #pragma unroll
    for (int it = 0; it < SIT; it++) {
        int k = tid + it * ST;
        int seg = myseg[it];
        if (seg != 0xFFFF) {
            int pos = atomicAdd(&s_cnt[seg], 1);
            s_list[pos] = (unsigned short)k;
        }
    }
    __syncthreads();

    const int nfg = s_P[NB];   // total fg elements

    // Pass 3: exact descending rank within group; scatter into order arrays.
    // Tie-break = reversed stable argsort: equal priority -> higher index first.
    #pragma unroll
    for (int it = 0; it < SIT; it++) {
        int k = tid + it * ST;
        int seg = myseg[it];
        if (seg != 0xFFFF) {
            int lo = s_P[seg], hi = s_P[seg + 1];
            float p = s_pri[k];
            int r = 0;
            for (int j = lo; j < hi; j++) {
                int o = s_list[j];
                float po = s_pri[o];
                if (po > p || (po == p && o > k)) r++;
            }
            int gend = (seg < NB) ? nfg : KK;
            int rank = (gend - hi) + r;     // #higher buckets in group + local rank
            if (seg < NB) {
                if (rank < NUM_FG_TARGET) s_ordF[rank] = (unsigned short)k;
            } else {
                if (rank < BATCH_PER_IMG) s_ordB[rank] = (unsigned short)k;
            }
        }
    }
    __syncthreads();

    // Final: assemble 512 samples (first 512 threads).
    if (tid < BATCH_PER_IMG) {
        int num_fg = nfg < NUM_FG_TARGET ? nfg : NUM_FG_TARGET;
        int nbg    = KK - nfg;
        int rem    = BATCH_PER_IMG - num_fg;
        int num_bg = nbg < rem ? nbg : rem;
        int tot    = num_fg + num_bg;
        int is64   = (s_nz == 0);

        float o_iou = 0.f;
        int o_idx = -1, o_cls = -1, o_gt = -1, o_val = 0;
        if (tid < tot) {
            int k = (tid < num_fg) ? (int)s_ordF[tid] : (int)s_ordB[tid - num_fg];
            float mv = mvb[k];
            int mi = (int)g_mi[(size_t)b * KK + k];
            int cls;
            if (mv >= 0.5f) {
                cls = is64 ? (int)((const long long*)gtcls)[b * MM + mi]
                           : ((const int*)gtcls)[b * MM + mi];
            } else {
                cls = NCLS;
            }
            o_iou = mv; o_idx = k; o_cls = cls; o_gt = mi; o_val = 1;
        }

        const int S = BB * BATCH_PER_IMG;
        int base = b * BATCH_PER_IMG + tid;
        out[base]         = o_iou;
        out[S + base]     = (float)o_idx;
        out[2 * S + base] = (float)o_cls;
        out[3 * S + base] = (float)o_gt;
        out[4 * S + base] = (float)o_val;
    }
}

// ---------------------------------------------------------------------------
extern "C" void kernel_launch(void* const* d_in, const int* in_sizes, int n_in,
                              void* d_out, int out_size) {
    const float* gt   = (const float*)d_in[0];   // [B, M, 4]
    const float* prop = (const float*)d_in[1];   // [B, N, 4]
    const void*  gtc  = d_in[2];                 // [B, M] int64 or int32
    const float* pri  = (const float*)d_in[3];   // [B, K]
    float* out = (float*)d_out;

    iou_kernel<<<dim3(8, BB), 256>>>(gt, prop);
    sample_kernel<<<BB, ST>>>(pri, gtc, out);
}

// round 6
// speedup vs baseline: 1.2485x; 1.1268x over previous
#include <cuda_runtime.h>

#define BB   64
#define MM   100
#define NN   4000
#define KK   4100          // N + M (proposal_append_gt)
#define NB   1024          // priority buckets per group
#define SEGS 2048          // 2 groups * NB
#define NCLS 80
#define BATCH_PER_IMG 512
#define NUM_FG_TARGET 128
#define ST   1024          // sample_kernel threads
#define SIT  5             // ceil(KK / ST)
#define LPI  2304          // lanes per image in iou_kernel (9 CTAs * 256)

// Scratch (static __device__ — no allocation)
__device__ float         g_mv[BB * KK];
__device__ unsigned char g_mi[BB * KK];

// ---------------------------------------------------------------------------
// Per-pair update. Pipe-balanced formulation:
//   max(x,0) = 0.5*(x+|x|)  (exact; |x| is a free operand modifier)
//   inter4 = (w+|w|)*(h+|h|) = 4*inter  (exact power-of-2 scaling)
//   uni    = fmaf(-0.25, inter4, S) = rnd(S - inter)   (bit-identical)
//   compare inter4*bu > bi4*uni  == 4*(inter*bu) > 4*(bi*uni)  (bit-identical)
// alu pipe: 4 FMNMX + FSETP + selects;  fma pipe: 4 FADD + FMUL + FFMA + 2 FMUL
// ---------------------------------------------------------------------------
__device__ __forceinline__ void iou_upd(float gx, float gy, float gz, float gw,
                                        float S, const float4& a,
                                        float& bi4, float& bu, int& bm, int m) {
    float lx = fmaxf(gx, a.x), ly = fmaxf(gy, a.y);
    float rx = fminf(gz, a.z), ry = fminf(gw, a.w);
    float w = rx - lx, h = ry - ly;
    float aw = w + fabsf(w);
    float ah = h + fabsf(h);
    float inter4 = aw * ah;
    float uni = fmaf(-0.25f, inter4, S);
    if (inter4 * bu > bi4 * uni) { bi4 = inter4; bu = uni; bm = m; }
}

// ---------------------------------------------------------------------------
// Kernel 1: per-(image, proposal) max-IoU matching.
// 2 proposals per thread (shared gt LDS), 2 parity chains per proposal.
// ---------------------------------------------------------------------------
__global__ __launch_bounds__(256) void iou_kernel(const float* __restrict__ gt,
                                                  const float* __restrict__ prop) {
    const int b   = blockIdx.y;
    const int tid = threadIdx.x;
    __shared__ float4 sgt[MM];
    __shared__ float  sarea[MM];

    if (tid < MM) {
        float4 g = reinterpret_cast<const float4*>(gt)[b * MM + tid];
        sgt[tid]   = g;
        sarea[tid] = (g.z - g.x) * (g.w - g.y);
    }
    __syncthreads();

    const float4* pr = reinterpret_cast<const float4*>(prop) + (size_t)b * NN;

    const int k0 = blockIdx.x * 256 + tid;   // [0, 2304) -> always a proposal (< NN)
    const int k1 = k0 + LPI;                 // [2304, 4608) -> may be gt or OOB
    float4 a0 = pr[k0];
    bool has1 = (k1 < KK);
    float4 a1 = a0;
    if (has1) a1 = (k1 < NN) ? pr[k1] : sgt[k1 - NN];

    float areaA0 = (a0.z - a0.x) * (a0.w - a0.y);
    float areaA1 = (a1.z - a1.x) * (a1.w - a1.y);

    // chains: [proposal][parity]
    float bi0e = 0.f, bu0e = 1.f; int bm0e = 0;
    float bi0o = 0.f, bu0o = 1.f; int bm0o = 1;
    float bi1e = 0.f, bu1e = 1.f; int bm1e = 0;
    float bi1o = 0.f, bu1o = 1.f; int bm1o = 1;

    #pragma unroll 4
    for (int m = 0; m < MM; m += 2) {
        {
            float4 g = sgt[m];
            float ga = sarea[m];
            iou_upd(g.x, g.y, g.z, g.w, ga + areaA0, a0, bi0e, bu0e, bm0e, m);
            iou_upd(g.x, g.y, g.z, g.w, ga + areaA1, a1, bi1e, bu1e, bm1e, m);
        }
        {
            float4 g = sgt[m + 1];
            float ga = sarea[m + 1];
            iou_upd(g.x, g.y, g.z, g.w, ga + areaA0, a0, bi0o, bu0o, bm0o, m + 1);
            iou_upd(g.x, g.y, g.z, g.w, ga + areaA1, a1, bi1o, bu1o, bm1o, m + 1);
        }
    }

    // merge parities (first-max tie-break: equal value -> lower index)
    {
        float c0 = bi0e * bu0o, c1 = bi0o * bu0e;
        bool useE = (c0 > c1) || (c0 == c1 && bm0e < bm0o);
        float bi = useE ? bi0e : bi0o;
        float bu = useE ? bu0e : bu0o;
        int   bm = useE ? bm0e : bm0o;
        size_t o = (size_t)b * KK + k0;
        g_mv[o] = __fdiv_rn(0.25f * bi, bu);
        g_mi[o] = (unsigned char)bm;
    }
    if (has1) {
        float c0 = bi1e * bu1o, c1 = bi1o * bu1e;
        bool useE = (c0 > c1) || (c0 == c1 && bm1e < bm1o);
        float bi = useE ? bi1e : bi1o;
        float bu = useE ? bu1e : bu1o;
        int   bm = useE ? bm1e : bm1o;
        size_t o = (size_t)b * KK + k1;
        g_mv[o] = __fdiv_rn(0.25f * bi, bu);
        g_mi[o] = (unsigned char)bm;
    }
}

// ---------------------------------------------------------------------------
// Kernel 2: per-image fg/bg subsampling via bucketed counting sort.
// One CTA (1024 threads) per image. Pass 3 prunes elements whose minimum
// possible rank already exceeds the group's selection limit.
// ---------------------------------------------------------------------------
__global__ __launch_bounds__(ST) void sample_kernel(const float* __restrict__ pri,
                                                    const void*  __restrict__ gtcls,
                                                    float* __restrict__ out) {
    const int b   = blockIdx.x;
    const int tid = threadIdx.x;

    __shared__ float          s_pri[KK];
    __shared__ unsigned short s_list[KK];
    __shared__ int            s_cnt[SEGS];     // histogram, then scatter cursor
    __shared__ int            s_P[SEGS + 1];   // ascending exclusive prefix
    __shared__ unsigned short s_ordF[NUM_FG_TARGET];
    __shared__ unsigned short s_ordB[BATCH_PER_IMG];
    __shared__ int            s_wsum[33];
    __shared__ int            s_nz;

    if (tid == 0) s_nz = 0;
    s_cnt[tid]      = 0;
    s_cnt[tid + ST] = 0;
    __syncthreads();

    // Parallel gt_classes dtype detect (int64 -> high words of first 64
    // elements are all zero). One global load per thread, no serial chain.
    if (tid < 64) {
        const int* w = (const int*)gtcls;
        if (w[2 * tid + 1] != 0) atomicOr(&s_nz, 1);
    }

    const float* prib = pri  + (size_t)b * KK;
    const float* mvb  = g_mv + (size_t)b * KK;

    // Pass 1: load priorities, classify fg/bg, histogram buckets.
    unsigned short myseg[SIT];
    #pragma unroll
    for (int it = 0; it < SIT; it++) {
        int k = tid + it * ST;
        if (k < KK) {
            float p = prib[k];
            s_pri[k] = p;
            float mv = mvb[k];
            int g  = (mv >= 0.5f) ? 0 : 1;           // 0 = fg, 1 = bg
            int bk = (int)(p * (float)NB);
            if (bk > NB - 1) bk = NB - 1;
            int seg = g * NB + bk;
            myseg[it] = (unsigned short)seg;
            atomicAdd(&s_cnt[seg], 1);
        } else {
            myseg[it] = 0xFFFF;
        }
    }
    __syncthreads();

    // Block exclusive scan over SEGS=2048 counts (2 per thread).
    const int i0 = tid * 2;
    int v0 = s_cnt[i0], v1 = s_cnt[i0 + 1];
    int t = v0 + v1;
    int lane = tid & 31, wid = tid >> 5;
    int incl = t;
    #pragma unroll
    for (int d = 1; d < 32; d <<= 1) {
        int n = __shfl_up_sync(0xffffffffu, incl, d);
        if (lane >= d) incl += n;
    }
    if (lane == 31) s_wsum[wid] = incl;
    __syncthreads();
    if (tid == 0) {
        int s = 0;
        #pragma unroll
        for (int i = 0; i < 32; i++) { int c = s_wsum[i]; s_wsum[i] = s; s += c; }
        s_wsum[32] = s;
    }
    __syncthreads();
    int ex = s_wsum[wid] + incl - t;
    s_P[i0]     = ex;
    s_P[i0 + 1] = ex + v0;
    if (tid == 0) s_P[SEGS] = KK;
    __syncthreads();

    // Re-init cnt as scatter cursor = P.
    s_cnt[i0]     = s_P[i0];
    s_cnt[i0 + 1] = s_P[i0 + 1];
    __syncthreads();

    // Pass 2: scatter element indices into bucket segments.
    #pragma unroll
    for (int it = 0; it < SIT; it++) {
        int k = tid + it * ST;
        int seg = myseg[it];
        if (seg != 0xFFFF) {
            int pos = atomicAdd(&s_cnt[seg], 1);
            s_list[pos] = (unsigned short)k;
        }
    }
    __syncthreads();

    const int nfg = s_P[NB];   // total fg elements

    // Pass 3: exact descending rank within group; scatter into order arrays.
    // Tie-break = reversed stable argsort: equal priority -> higher index first.
    // Prune: min possible rank = (#elements in strictly-higher buckets) =
    // gend - hi; if already >= group limit, element can never be selected.
    #pragma unroll
    for (int it = 0; it < SIT; it++) {
        int k = tid + it * ST;
        int seg = myseg[it];
        if (seg != 0xFFFF) {
            bool isfg  = seg < NB;
            int  gend  = isfg ? nfg : KK;
            int  limit = isfg ? NUM_FG_TARGET : BATCH_PER_IMG;
            int  hi    = s_P[seg + 1];
            int  base_rank = gend - hi;
            if (base_rank < limit) {
                int lo = s_P[seg];
                float p = s_pri[k];
                int r = 0;
                for (int j = lo; j < hi; j++) {
                    int o = s_list[j];
                    float po = s_pri[o];
                    if (po > p || (po == p && o > k)) r++;
                }
                int rank = base_rank + r;
                if (isfg) {
                    if (rank < NUM_FG_TARGET) s_ordF[rank] = (unsigned short)k;
                } else {
                    if (rank < BATCH_PER_IMG) s_ordB[rank] = (unsigned short)k;
                }
            }
        }
    }
    __syncthreads();

    // Final: assemble 512 samples (first 512 threads).
    if (tid < BATCH_PER_IMG) {
        int num_fg = nfg < NUM_FG_TARGET ? nfg : NUM_FG_TARGET;
        int nbg    = KK - nfg;
        int rem    = BATCH_PER_IMG - num_fg;
        int num_bg = nbg < rem ? nbg : rem;
        int tot    = num_fg + num_bg;
        int is64   = (s_nz == 0);

        float o_iou = 0.f;
        int o_idx = -1, o_cls = -1, o_gt = -1, o_val = 0;
        if (tid < tot) {
            int k = (tid < num_fg) ? (int)s_ordF[tid] : (int)s_ordB[tid - num_fg];
            float mv = mvb[k];
            int mi = (int)g_mi[(size_t)b * KK + k];
            int cls;
            if (mv >= 0.5f) {
                cls = is64 ? (int)((const long long*)gtcls)[b * MM + mi]
                           : ((const int*)gtcls)[b * MM + mi];
            } else {
                cls = NCLS;
            }
            o_iou = mv; o_idx = k; o_cls = cls; o_gt = mi; o_val = 1;
        }

        const int S = BB * BATCH_PER_IMG;
        int base = b * BATCH_PER_IMG + tid;
        out[base]         = o_iou;
        out[S + base]     = (float)o_idx;
        out[2 * S + base] = (float)o_cls;
        out[3 * S + base] = (float)o_gt;
        out[4 * S + base] = (float)o_val;
    }
}

// ---------------------------------------------------------------------------
extern "C" void kernel_launch(void* const* d_in, const int* in_sizes, int n_in,
                              void* d_out, int out_size) {
    const float* gt   = (const float*)d_in[0];   // [B, M, 4]
    const float* prop = (const float*)d_in[1];   // [B, N, 4]
    const void*  gtc  = d_in[2];                 // [B, M] int64 or int32
    const float* pri  = (const float*)d_in[3];   // [B, K]
    float* out = (float*)d_out;

    iou_kernel<<<dim3(9, BB), 256>>>(gt, prop);
    sample_kernel<<<BB, ST>>>(pri, gtc, out);
}

// round 7
// speedup vs baseline: 1.2613x; 1.0102x over previous
#include <cuda_runtime.h>

#define BB   64
#define MM   100
#define NN   4000
#define KK   4100          // N + M (proposal_append_gt)
#define NB   1024          // priority buckets per group
#define SEGS 2048          // 2 groups * NB
#define NCLS 80
#define BATCH_PER_IMG 512
#define NUM_FG_TARGET 128
#define ST   1024          // sample_kernel threads
#define SIT  5             // ceil(KK / ST)
#define LPI  2304          // lanes per image in iou_kernel (9 CTAs * 256)
#define TBF  0.75f         // bg candidate priority threshold

// Scratch (static __device__ — no allocation)
__device__ float         g_mv[BB * KK];
__device__ unsigned char g_mi[BB * KK];

// ---------------------------------------------------------------------------
// Per-pair update. iou = inter/(S-inter) is strictly monotone in inter/S,
// so argmax can compare inter4_i * S_j vs inter4_j * S_i (no union needed
// per pair; union computed once per proposal from the winner).
//   max(x,0) = 0.5*(x+|x|)  (exact; |x| is a free operand modifier)
//   inter4 = (w+|w|)*(h+|h|) = 4*inter  (exact power-of-2 scaling)
// fma pipe: 2 FADD(w,h) + 2 FADD(aw,ah) + FMUL(inter4) + 2 FMUL(cmp) + FADD(S)
// alu pipe: 4 FMNMX + FSETP + 3 SEL
// ---------------------------------------------------------------------------
__device__ __forceinline__ void iou_upd(float gx, float gy, float gz, float gw,
                                        float S, const float4& a,
                                        float& bi4, float& bS, int& bm, int m) {
    float lx = fmaxf(gx, a.x), ly = fmaxf(gy, a.y);
    float rx = fminf(gz, a.z), ry = fminf(gw, a.w);
    float w = rx - lx, h = ry - ly;
    float aw = w + fabsf(w);
    float ah = h + fabsf(h);
    float inter4 = aw * ah;
    if (inter4 * bS > bi4 * S) { bi4 = inter4; bS = S; bm = m; }
}

__device__ __forceinline__ void iou_finish(float bi4, float bS, int bm,
                                           int b, int k) {
    float uni = fmaf(-0.25f, bi4, bS);      // = rnd(S - inter), bit-identical
    size_t o = (size_t)b * KK + k;
    g_mv[o] = __fdiv_rn(0.25f * bi4, uni);  // all-zero case: 0/1 = 0 (bS init 1)
    g_mi[o] = (unsigned char)bm;
}

// ---------------------------------------------------------------------------
// Kernel 1: per-(image, proposal) max-IoU matching.
// 2 proposals per thread (shared gt LDS), 2 parity chains per proposal.
// ---------------------------------------------------------------------------
__global__ __launch_bounds__(256) void iou_kernel(const float* __restrict__ gt,
                                                  const float* __restrict__ prop) {
    const int b   = blockIdx.y;
    const int tid = threadIdx.x;
    __shared__ float4 sgt[MM];
    __shared__ float  sarea[MM];

    if (tid < MM) {
        float4 g = reinterpret_cast<const float4*>(gt)[b * MM + tid];
        sgt[tid]   = g;
        sarea[tid] = (g.z - g.x) * (g.w - g.y);
    }
    __syncthreads();

    const float4* pr = reinterpret_cast<const float4*>(prop) + (size_t)b * NN;

    const int k0 = blockIdx.x * 256 + tid;   // [0, 2304) -> always a proposal (< NN)
    const int k1 = k0 + LPI;                 // [2304, 4608) -> may be gt or OOB
    float4 a0 = pr[k0];
    bool has1 = (k1 < KK);
    float4 a1 = a0;
    if (has1) a1 = (k1 < NN) ? pr[k1] : sgt[k1 - NN];

    float areaA0 = (a0.z - a0.x) * (a0.w - a0.y);
    float areaA1 = (a1.z - a1.x) * (a1.w - a1.y);

    // chains: [proposal][parity]; bS holds S (=areaG+areaA) of current best
    float bi0e = 0.f, bS0e = 1.f; int bm0e = 0;
    float bi0o = 0.f, bS0o = 1.f; int bm0o = 1;
    float bi1e = 0.f, bS1e = 1.f; int bm1e = 0;
    float bi1o = 0.f, bS1o = 1.f; int bm1o = 1;

    #pragma unroll 4
    for (int m = 0; m < MM; m += 2) {
        {
            float4 g = sgt[m];
            float ga = sarea[m];
            iou_upd(g.x, g.y, g.z, g.w, ga + areaA0, a0, bi0e, bS0e, bm0e, m);
            iou_upd(g.x, g.y, g.z, g.w, ga + areaA1, a1, bi1e, bS1e, bm1e, m);
        }
        {
            float4 g = sgt[m + 1];
            float ga = sarea[m + 1];
            iou_upd(g.x, g.y, g.z, g.w, ga + areaA0, a0, bi0o, bS0o, bm0o, m + 1);
            iou_upd(g.x, g.y, g.z, g.w, ga + areaA1, a1, bi1o, bS1o, bm1o, m + 1);
        }
    }

    // merge parities (first-max tie-break: equal value -> lower index)
    {
        float c0 = bi0e * bS0o, c1 = bi0o * bS0e;
        bool useE = (c0 > c1) || (c0 == c1 && bm0e < bm0o);
        iou_finish(useE ? bi0e : bi0o, useE ? bS0e : bS0o, useE ? bm0e : bm0o, b, k0);
    }
    if (has1) {
        float c0 = bi1e * bS1o, c1 = bi1o * bS1e;
        bool useE = (c0 > c1) || (c0 == c1 && bm1e < bm1o);
        iou_finish(useE ? bi1e : bi1o, useE ? bS1e : bS1o, useE ? bm1e : bm1o, b, k1);
    }
}

// ---------------------------------------------------------------------------
// Kernel 2: per-image fg/bg subsampling via bucketed counting sort over
// CANDIDATES only. bg elements with p < TBF can never be among the top-512
// bg when >= 512 bg have p >= TBF (ballot-verified; exact fallback to all
// otherwise), so they skip the histogram/scatter/rank machinery entirely.
// This cuts shared-atomic (ATOMS) traffic ~4x — the measured bottleneck.
// ---------------------------------------------------------------------------
__global__ __launch_bounds__(ST) void sample_kernel(const float* __restrict__ pri,
                                                    const void*  __restrict__ gtcls,
                                                    float* __restrict__ out) {
    const int b   = blockIdx.x;
    const int tid = threadIdx.x;

    __shared__ float          s_pri[KK];
    __shared__ unsigned short s_list[KK];
    __shared__ int            s_cnt[SEGS];     // histogram, then scatter cursor
    __shared__ int            s_P[SEGS + 1];   // ascending exclusive prefix
    __shared__ unsigned short s_ordF[NUM_FG_TARGET];
    __shared__ unsigned short s_ordB[BATCH_PER_IMG];
    __shared__ int            s_wsum[33];
    __shared__ int            s_nz;
    __shared__ int            s_cbg;

    if (tid == 0) { s_nz = 0; s_cbg = 0; }
    s_cnt[tid]      = 0;
    s_cnt[tid + ST] = 0;
    __syncthreads();

    // Parallel gt_classes dtype detect (int64 -> high words of first 64
    // elements are all zero).
    if (tid < 64) {
        const int* w = (const int*)gtcls;
        if (w[2 * tid + 1] != 0) atomicOr(&s_nz, 1);
    }

    const float* prib = pri  + (size_t)b * KK;
    const float* mvb  = g_mv + (size_t)b * KK;

    // Pass 0: load priority + fg flag into registers, count bg candidates
    // (atomic-free warp ballots; one shared atomic per warp).
    float pv[SIT];
    bool  fgv[SIT];
    unsigned bgc = 0;
    #pragma unroll
    for (int it = 0; it < SIT; it++) {
        int k = tid + it * ST;
        float p = -1.f;
        bool fg = false;
        if (k < KK) {
            p = prib[k];
            s_pri[k] = p;
            fg = (mvb[k] >= 0.5f);
        }
        pv[it] = p;
        fgv[it] = fg;
        unsigned msk = __ballot_sync(0xffffffffu, (!fg) && (p >= TBF));
        if ((tid & 31) == 0) bgc += __popc(msk);
    }
    if ((tid & 31) == 0 && bgc) atomicAdd(&s_cbg, (int)bgc);
    __syncthreads();

    const float tbeff = (s_cbg >= BATCH_PER_IMG) ? TBF : -1e30f;

    // Pass 1: histogram candidates (all fg; bg with p >= threshold).
    unsigned short myseg[SIT];
    #pragma unroll
    for (int it = 0; it < SIT; it++) {
        int k = tid + it * ST;
        unsigned short sg = 0xFFFF;
        if (k < KK) {
            float p = pv[it];
            bool cand = fgv[it] || (p >= tbeff);
            if (cand) {
                int bk = (int)(p * (float)NB);
                if (bk > NB - 1) bk = NB - 1;
                if (bk < 0) bk = 0;
                int seg = (fgv[it] ? 0 : NB) + bk;
                sg = (unsigned short)seg;
                atomicAdd(&s_cnt[seg], 1);
            }
        }
        myseg[it] = sg;
    }
    __syncthreads();

    // Block exclusive scan over SEGS=2048 counts (2 per thread).
    const int i0 = tid * 2;
    int v0 = s_cnt[i0], v1 = s_cnt[i0 + 1];
    int t = v0 + v1;
    int lane = tid & 31, wid = tid >> 5;
    int incl = t;
    #pragma unroll
    for (int d = 1; d < 32; d <<= 1) {
        int n = __shfl_up_sync(0xffffffffu, incl, d);
        if (lane >= d) incl += n;
    }
    if (lane == 31) s_wsum[wid] = incl;
    __syncthreads();
    if (tid == 0) {
        int s = 0;
        #pragma unroll
        for (int i = 0; i < 32; i++) { int c = s_wsum[i]; s_wsum[i] = s; s += c; }
        s_wsum[32] = s;
    }
    __syncthreads();
    int ex = s_wsum[wid] + incl - t;
    s_P[i0]     = ex;
    s_P[i0 + 1] = ex + v0;
    if (tid == 0) s_P[SEGS] = s_wsum[32];    // total candidates
    __syncthreads();

    // Re-init cnt as scatter cursor = P.
    s_cnt[i0]     = s_P[i0];
    s_cnt[i0 + 1] = s_P[i0 + 1];
    __syncthreads();

    // Pass 2: scatter candidate indices into bucket segments.
    #pragma unroll
    for (int it = 0; it < SIT; it++) {
        int seg = myseg[it];
        if (seg != 0xFFFF) {
            int k = tid + it * ST;
            int pos = atomicAdd(&s_cnt[seg], 1);
            s_list[pos] = (unsigned short)k;
        }
    }
    __syncthreads();

    const int nfg     = s_P[NB];     // total fg (all fg are candidates)
    const int candTot = s_P[SEGS];   // total candidates

    // Pass 3: exact descending rank within group; scatter into order arrays.
    // Candidate ranks == true group ranks (excluded bg are strictly lower).
    // Tie-break = reversed stable argsort: equal priority -> higher index first.
    #pragma unroll
    for (int it = 0; it < SIT; it++) {
        int seg = myseg[it];
        if (seg != 0xFFFF) {
            int  k     = tid + it * ST;
            bool isfg  = seg < NB;
            int  gend  = isfg ? nfg : candTot;
            int  limit = isfg ? NUM_FG_TARGET : BATCH_PER_IMG;
            int  hi    = s_P[seg + 1];
            int  base_rank = gend - hi;      // elements in strictly-higher buckets
            if (base_rank < limit) {
                int lo = s_P[seg];
                float p = s_pri[k];
                int r = 0;
                for (int j = lo; j < hi; j++) {
                    int o = s_list[j];
                    float po = s_pri[o];
                    if (po > p || (po == p && o > k)) r++;
                }
                int rank = base_rank + r;
                if (isfg) {
                    if (rank < NUM_FG_TARGET) s_ordF[rank] = (unsigned short)k;
                } else {
                    if (rank < BATCH_PER_IMG) s_ordB[rank] = (unsigned short)k;
                }
            }
        }
    }
    __syncthreads();

    // Final: assemble 512 samples (first 512 threads).
    if (tid < BATCH_PER_IMG) {
        int num_fg = nfg < NUM_FG_TARGET ? nfg : NUM_FG_TARGET;
        int nbg    = KK - nfg;               // FULL bg count, not candidates
        int rem    = BATCH_PER_IMG - num_fg;
        int num_bg = nbg < rem ? nbg : rem;
        int tot    = num_fg + num_bg;
        int is64   = (s_nz == 0);

        float o_iou = 0.f;
        int o_idx = -1, o_cls = -1, o_gt = -1, o_val = 0;
        if (tid < tot) {
            int k = (tid < num_fg) ? (int)s_ordF[tid] : (int)s_ordB[tid - num_fg];
            float mv = mvb[k];
            int mi = (int)g_mi[(size_t)b * KK + k];
            int cls;
            if (mv >= 0.5f) {
                cls = is64 ? (int)((const long long*)gtcls)[b * MM + mi]
                           : ((const int*)gtcls)[b * MM + mi];
            } else {
                cls = NCLS;
            }
            o_iou = mv; o_idx = k; o_cls = cls; o_gt = mi; o_val = 1;
        }

        const int S = BB * BATCH_PER_IMG;
        int base = b * BATCH_PER_IMG + tid;
        out[base]         = o_iou;
        out[S + base]     = (float)o_idx;
        out[2 * S + base] = (float)o_cls;
        out[3 * S + base] = (float)o_gt;
        out[4 * S + base] = (float)o_val;
    }
}

// ---------------------------------------------------------------------------
extern "C" void kernel_launch(void* const* d_in, const int* in_sizes, int n_in,
                              void* d_out, int out_size) {
    const float* gt   = (const float*)d_in[0];   // [B, M, 4]
    const float* prop = (const float*)d_in[1];   // [B, N, 4]
    const void*  gtc  = d_in[2];                 // [B, M] int64 or int32
    const float* pri  = (const float*)d_in[3];   // [B, K]
    float* out = (float*)d_out;

    iou_kernel<<<dim3(9, BB), 256>>>(gt, prop);
    sample_kernel<<<BB, ST>>>(pri, gtc, out);
}